// round 16
// baseline (speedup 1.0000x reference)
#include <cuda_runtime.h>
#include <cuda_fp16.h>
#include <cstdint>

#define D_MODEL   512
#define THREE_D   1536
#define M_TOK     32768      // 8 * 64 * 64 tokens
#define N_HEAD    16
#define HEAD_DIM  32
#define SCALE_Q   0.17677669529663689f   // 1/sqrt(32)
#define STAGES    3
#define NKT       16         // 512 / 32 halves per k-tile
#define ROWB      80         // smem row stride bytes (32 halves + 16B pad)
#define TILEB     (128 * ROWB)          // 10240 per operand tile
#define STAGEB    (2 * TILEB)           // 20480 per stage

// Device-global scratch (allocation-guard-safe)
__device__ __half g_xh[(size_t)M_TOK * D_MODEL];         // 32 MB  fp16 x
__device__ __half g_wh[(size_t)THREE_D * D_MODEL];       // 1.5 MB fp16 w
// qkv outputs (token-major [tok][32] per head slice), pre-split fp16
__device__ __half g_qh[(size_t)M_TOK * D_MODEL];
__device__ __half g_ql[(size_t)M_TOK * D_MODEL];
__device__ __half g_kh[(size_t)M_TOK * D_MODEL];
__device__ __half g_kl[(size_t)M_TOK * D_MODEL];
__device__ __half g_vh[(size_t)M_TOK * D_MODEL];

__device__ __forceinline__ void mma_f16(float* c, const uint32_t* a,
                                        uint32_t b0, uint32_t b1) {
    asm volatile(
        "mma.sync.aligned.m16n8k16.row.col.f32.f16.f16.f32 "
        "{%0,%1,%2,%3}, {%4,%5,%6,%7}, {%8,%9}, {%0,%1,%2,%3};\n"
        : "+f"(c[0]), "+f"(c[1]), "+f"(c[2]), "+f"(c[3])
        : "r"(a[0]), "r"(a[1]), "r"(a[2]), "r"(a[3]), "r"(b0), "r"(b1));
}

__device__ __forceinline__ void ldsm4(uint32_t& r0, uint32_t& r1, uint32_t& r2,
                                      uint32_t& r3, uint32_t addr) {
    asm volatile("ldmatrix.sync.aligned.m8n8.x4.shared.b16 {%0,%1,%2,%3}, [%4];"
                 : "=r"(r0), "=r"(r1), "=r"(r2), "=r"(r3) : "r"(addr));
}

__device__ __forceinline__ void ldsm2(uint32_t& r0, uint32_t& r1, uint32_t addr) {
    asm volatile("ldmatrix.sync.aligned.m8n8.x2.shared.b16 {%0,%1}, [%2];"
                 : "=r"(r0), "=r"(r1) : "r"(addr));
}

__device__ __forceinline__ void split_h2(float x, float y, __half2& hi, __half2& lo) {
    hi = __floats2half2_rn(x, y);
    lo = __floats2half2_rn(x - __low2float(hi), y - __high2float(hi));
}

__device__ __forceinline__ uint32_t h2u(__half2 h) {
    return *reinterpret_cast<uint32_t*>(&h);
}

__device__ __forceinline__ void cp16(uint32_t saddr, const void* g) {
    asm volatile("cp.async.cg.shared.global [%0], [%1], 16;"
                 :: "r"(saddr), "l"(g));
}

// ---------------------------------------------------------------------------
// Pre-pass: f32 -> f16 (RN). Each thread converts 8 values (16B store).
// ---------------------------------------------------------------------------
__global__ void to_half(const float* __restrict__ in, __half* __restrict__ out, int n8) {
    int i = blockIdx.x * 256 + threadIdx.x;
    if (i >= n8) return;
    float4 v0 = ((const float4*)in)[2 * i];
    float4 v1 = ((const float4*)in)[2 * i + 1];
    __half2 h[4];
    h[0] = __floats2half2_rn(v0.x, v0.y);
    h[1] = __floats2half2_rn(v0.z, v0.w);
    h[2] = __floats2half2_rn(v1.x, v1.y);
    h[3] = __floats2half2_rn(v1.z, v1.w);
    ((uint4*)out)[i] = *(uint4*)h;
}

// ---------------------------------------------------------------------------
// Kernel 1: qkv = xh @ wh^T + b  (fp16 mma m16n8k16, cp.async 3-stage).
// Staged SMEM epilogue -> coalesced 16B fp16 stores (R13 config, best known).
// ---------------------------------------------------------------------------
#define SROW 132   // f32 stage row stride (128 + 4)

__global__ __launch_bounds__(256, 2)
void qkv_gemm_f16(const __half* __restrict__ xh,
                  const __half* __restrict__ wh,
                  const float* __restrict__ bias_vec,
                  __half* __restrict__ qh, __half* __restrict__ ql,
                  __half* __restrict__ kh, __half* __restrict__ kl,
                  __half* __restrict__ vh) {
    extern __shared__ char smem[];   // STAGES*20480 pipeline, reused as stage
    __shared__ float biasS[128];
    const uint32_t smem_base = (uint32_t)__cvta_generic_to_shared(smem);

    const int tid  = threadIdx.x;
    const int lane = tid & 31, warp = tid >> 5;
    const int wm = warp >> 2, wn = warp & 3;        // 2 x 4 warp grid
    const int bm = blockIdx.y * 128, bn = blockIdx.x * 128;

    if (tid < 128) biasS[tid] = bias_vec[bn + tid];

    const __half* aptr[2];
    const __half* bptr[2];
    uint32_t soff[2];
#pragma unroll
    for (int i = 0; i < 2; ++i) {
        const int id  = i * 256 + tid;              // 0..511
        const int row = id >> 2, c = id & 3;
        soff[i] = (uint32_t)(row * ROWB + c * 16);
        aptr[i] = xh + (size_t)(bm + row) * D_MODEL + c * 8;
        bptr[i] = wh + (size_t)(bn + row) * D_MODEL + c * 8;
    }

    auto issue = [&](int kt, int s) {
        const uint32_t ab = smem_base + s * STAGEB;
        const uint32_t bb = ab + TILEB;
#pragma unroll
        for (int i = 0; i < 2; ++i) {
            cp16(ab + soff[i], aptr[i] + kt * 32);
            cp16(bb + soff[i], bptr[i] + kt * 32);
        }
        asm volatile("cp.async.commit_group;");
    };

    float acc[4][4][4];
#pragma unroll
    for (int m = 0; m < 4; ++m)
#pragma unroll
        for (int n = 0; n < 4; ++n)
#pragma unroll
            for (int q = 0; q < 4; ++q) acc[m][n][q] = 0.f;

    const int laneR8 = lane & 7;
    const int aRow   = laneR8 + ((lane >> 3) & 1) * 8;
    const int aChunk = lane >> 4;
    const int bRow   = laneR8;
    const int bChunk = (lane >> 3) & 1;

    issue(0, 0);
    issue(1, 1);

    for (int kt = 0; kt < NKT; ++kt) {
        if (kt == NKT - 1) asm volatile("cp.async.wait_group 0;");
        else               asm volatile("cp.async.wait_group 1;");
        __syncthreads();

        const int s = kt % STAGES;
        const uint32_t abase = smem_base + s * STAGEB;
        const uint32_t bbase = abase + TILEB;

#pragma unroll
        for (int ks = 0; ks < 2; ++ks) {
            uint32_t af[4][4];
#pragma unroll
            for (int mf = 0; mf < 4; ++mf) {
                const int row = wm * 64 + mf * 16 + aRow;
                ldsm4(af[mf][0], af[mf][1], af[mf][2], af[mf][3],
                      abase + (uint32_t)(row * ROWB + (ks * 2 + aChunk) * 16));
            }
            uint32_t bf[4][2];
#pragma unroll
            for (int nf = 0; nf < 4; ++nf) {
                const int row = wn * 32 + nf * 8 + bRow;
                ldsm2(bf[nf][0], bf[nf][1],
                      bbase + (uint32_t)(row * ROWB + (ks * 2 + bChunk) * 16));
            }
#pragma unroll
            for (int mf = 0; mf < 4; ++mf)
#pragma unroll
                for (int nf = 0; nf < 4; ++nf)
                    mma_f16(acc[mf][nf], af[mf], bf[nf][0], bf[nf][1]);
        }

        if (kt + 2 < NKT) issue(kt + 2, (kt + 2) % STAGES);
    }

    // ---- staged epilogue: 2 passes of 64 rows ----
    const int grp = blockIdx.x >> 2;           // 0=q, 1=k, 2=v
    const int cb  = bn - grp * 512;            // col base within 512-wide array
    const int gq = lane >> 2, tq = lane & 3;
    float* stage = (float*)smem;               // 64 x SROW f32

#pragma unroll
    for (int h = 0; h < 2; ++h) {
        __syncthreads();
        if (wm == h) {
#pragma unroll
            for (int m = 0; m < 4; ++m) {
                const int r0 = m * 16 + gq;
#pragma unroll
                for (int n = 0; n < 4; ++n) {
                    const int c = wn * 32 + n * 8 + tq * 2;
                    *(float2*)&stage[r0 * SROW + c] =
                        make_float2(acc[m][n][0], acc[m][n][1]);
                    *(float2*)&stage[(r0 + 8) * SROW + c] =
                        make_float2(acc[m][n][2], acc[m][n][3]);
                }
            }
        }
        __syncthreads();

#pragma unroll
        for (int u4 = 0; u4 < 4; ++u4) {
            const int u   = u4 * 256 + tid;    // 0..1023
            const int row = u >> 4, ch = u & 15;
            float4 v0 = *(const float4*)&stage[row * SROW + ch * 8];
            float4 v1 = *(const float4*)&stage[row * SROW + ch * 8 + 4];
            float f[8] = {v0.x, v0.y, v0.z, v0.w, v1.x, v1.y, v1.z, v1.w};
#pragma unroll
            for (int i = 0; i < 8; ++i) f[i] += biasS[ch * 8 + i];
            const size_t ga = (size_t)(bm + h * 64 + row) * D_MODEL + cb + ch * 8;
            if (grp == 0) {
#pragma unroll
                for (int i = 0; i < 8; ++i) f[i] *= SCALE_Q;
                __half2 hi[4], lo[4];
#pragma unroll
                for (int i = 0; i < 4; ++i)
                    split_h2(f[2 * i], f[2 * i + 1], hi[i], lo[i]);
                *(uint4*)(qh + ga) = *(uint4*)hi;
                *(uint4*)(ql + ga) = *(uint4*)lo;
            } else if (grp == 1) {
                __half2 hi[4], lo[4];
#pragma unroll
                for (int i = 0; i < 4; ++i)
                    split_h2(f[2 * i], f[2 * i + 1], hi[i], lo[i]);
                *(uint4*)(kh + ga) = *(uint4*)hi;
                *(uint4*)(kl + ga) = *(uint4*)lo;
            } else {
                __half2 hi[4];
#pragma unroll
                for (int i = 0; i < 4; ++i)
                    hi[i] = __floats2half2_rn(f[2 * i], f[2 * i + 1]);
                *(uint4*)(vh + ga) = *(uint4*)hi;
            }
        }
    }
}

// ---------------------------------------------------------------------------
// Kernel 2: per (window, head) attention via fp16 mma (R13 math).
// Changes: reversed window order (L2 reuse of freshly-written qkv) and
// launch_bounds(128, 8) (regs<=64 -> 8 CTAs/SM).
// ---------------------------------------------------------------------------
__device__ __forceinline__ int region_id(int g) {
    return g < 56 ? 0 : (g < 60 ? 1 : 2);
}

#define SQK 40
#define SVP 72

__global__ __launch_bounds__(128, 8)
void win_attn_f16(const __half* __restrict__ qh, const __half* __restrict__ ql,
                  const __half* __restrict__ kh, const __half* __restrict__ kl,
                  const __half* __restrict__ vh,
                  const float* __restrict__ bias_table, float* __restrict__ out) {
    const int head = blockIdx.x;
    const int wdx  = 511 - (int)blockIdx.y;   // reverse: read freshest qkv first
    const int n  = wdx >> 6;
    const int rr = wdx & 63;
    const int wh = rr >> 3;
    const int ww = rr & 7;

    __shared__ __half Qh[64 * SQK], Ql[64 * SQK];
    __shared__ __half Kh[64 * SQK], Kl[64 * SQK];
    __shared__ __half Vth[32 * SVP];                  // transposed hi: [d][j]
    __shared__ float bias_s[228];

    const int tid  = threadIdx.x;
    const int lane = tid & 31, warp = tid >> 5;
    const int ra  = lane >> 2;
    const int ca2 = (lane & 3) * 2;

    const uint32_t sQh = (uint32_t)__cvta_generic_to_shared(Qh);
    const uint32_t sQl = (uint32_t)__cvta_generic_to_shared(Ql);
    const uint32_t sKh = (uint32_t)__cvta_generic_to_shared(Kh);
    const uint32_t sKl = (uint32_t)__cvta_generic_to_shared(Kl);

    // ---- Q/K hi/lo: direct cp.async copies ----
#pragma unroll
    for (int p = 0; p < 2; ++p) {
        const int u   = p * 128 + tid;              // 0..255
        const int row = u >> 2, c = u & 3;          // row 0..63, 16B chunk 0..3
        const int tok = ((n * 64 + wh * 8 + (row >> 3)) * 64 + ww * 8 + (row & 7));
        const size_t gb = (size_t)tok * D_MODEL + head * HEAD_DIM + c * 8;
        const uint32_t so = (uint32_t)(row * ROWB + c * 16);
        cp16(sQh + so, qh + gb);
        cp16(sQl + so, ql + gb);
        cp16(sKh + so, kh + gb);
        cp16(sKl + so, kl + gb);
    }
    asm volatile("cp.async.commit_group;");

    for (int i = tid; i < 225; i += 128)
        bias_s[i] = bias_table[i * N_HEAD + head];

    // ---- V transposed (hi): PRMT interleave of row pairs ----
#pragma unroll
    for (int pass = 0; pass < 2; ++pass) {
        const int idx = pass * 128 + tid;           // 0..255
        const int jp  = idx & 31;
        const int d4  = (idx >> 5) * 4;
        const int j0  = 2 * jp, j1 = 2 * jp + 1;
        const int t0 = ((n * 64 + wh * 8 + (j0 >> 3)) * 64 + ww * 8 + (j0 & 7));
        const int t1 = ((n * 64 + wh * 8 + (j1 >> 3)) * 64 + ww * 8 + (j1 & 7));
        uint2 a = *(const uint2*)(vh + (size_t)t0 * D_MODEL + head * HEAD_DIM + d4);
        uint2 b = *(const uint2*)(vh + (size_t)t1 * D_MODEL + head * HEAD_DIM + d4);
        *(uint32_t*)&Vth[(d4 + 0) * SVP + j0] = __byte_perm(a.x, b.x, 0x5410);
        *(uint32_t*)&Vth[(d4 + 1) * SVP + j0] = __byte_perm(a.x, b.x, 0x7632);
        *(uint32_t*)&Vth[(d4 + 2) * SVP + j0] = __byte_perm(a.y, b.y, 0x5410);
        *(uint32_t*)&Vth[(d4 + 3) * SVP + j0] = __byte_perm(a.y, b.y, 0x7632);
    }
    asm volatile("cp.async.wait_group 0;");
    __syncthreads();

    const int m0 = warp * 16;

    // ---- phase 1: S = Q K^T (split-fp16, 3 mma per step) ----
    float acc[8][4];
#pragma unroll
    for (int nf = 0; nf < 8; ++nf)
#pragma unroll
        for (int q = 0; q < 4; ++q) acc[nf][q] = 0.f;

#pragma unroll
    for (int ks = 0; ks < 2; ++ks) {
        const int k0 = ks * 16;
        const int ro = (m0 + ra) * SQK + k0 + ca2;
        uint32_t ah[4], al[4];
        ah[0] = *(const uint32_t*)&Qh[ro];
        ah[1] = *(const uint32_t*)&Qh[ro + 8 * SQK];
        ah[2] = *(const uint32_t*)&Qh[ro + 8];
        ah[3] = *(const uint32_t*)&Qh[ro + 8 * SQK + 8];
        al[0] = *(const uint32_t*)&Ql[ro];
        al[1] = *(const uint32_t*)&Ql[ro + 8 * SQK];
        al[2] = *(const uint32_t*)&Ql[ro + 8];
        al[3] = *(const uint32_t*)&Ql[ro + 8 * SQK + 8];
#pragma unroll
        for (int nf = 0; nf < 8; ++nf) {
            const int ko = (nf * 8 + ra) * SQK + k0 + ca2;
            const uint32_t bh0 = *(const uint32_t*)&Kh[ko];
            const uint32_t bh1 = *(const uint32_t*)&Kh[ko + 8];
            const uint32_t bl0 = *(const uint32_t*)&Kl[ko];
            const uint32_t bl1 = *(const uint32_t*)&Kl[ko + 8];
            mma_f16(acc[nf], ah, bh0, bh1);
            mma_f16(acc[nf], ah, bl0, bl1);
            mma_f16(acc[nf], al, bh0, bh1);
        }
    }

    // ---- phase 2: bias + mask + softmax; keep P in registers ----
    float pv[2][16];
#pragma unroll
    for (int h = 0; h < 2; ++h) {
        const int i  = m0 + ra + 8 * h;
        const int ih = i >> 3, iw = i & 7;
        const int mi = region_id(wh * 8 + ih) * 3 + region_id(ww * 8 + iw);

#pragma unroll
        for (int nf = 0; nf < 8; ++nf) {
            const int d0row = (ih - nf + 7) * 15;
            const int regh3 = region_id(wh * 8 + nf) * 3;
#pragma unroll
            for (int e = 0; e < 2; ++e) {
                const int j = ca2 + e;
                float v = acc[nf][2 * h + e] + bias_s[d0row + (iw - j + 7)];
                if (mi != regh3 + region_id(ww * 8 + j)) v -= 100.f;
                pv[h][nf * 2 + e] = v;
            }
        }
        float mx = pv[h][0];
#pragma unroll
        for (int q = 1; q < 16; ++q) mx = fmaxf(mx, pv[h][q]);
        mx = fmaxf(mx, __shfl_xor_sync(0xffffffffu, mx, 1));
        mx = fmaxf(mx, __shfl_xor_sync(0xffffffffu, mx, 2));
        float sum = 0.f;
#pragma unroll
        for (int q = 0; q < 16; ++q) { pv[h][q] = __expf(pv[h][q] - mx); sum += pv[h][q]; }
        sum += __shfl_xor_sync(0xffffffffu, sum, 1);
        sum += __shfl_xor_sync(0xffffffffu, sum, 2);
        const float inv = 1.0f / sum;
#pragma unroll
        for (int q = 0; q < 16; ++q) pv[h][q] *= inv;
    }

    // ---- phase 3: O = P V  (hi-fp16) ----
    float oacc[4][4];
#pragma unroll
    for (int nf = 0; nf < 4; ++nf)
#pragma unroll
        for (int q = 0; q < 4; ++q) oacc[nf][q] = 0.f;

#pragma unroll
    for (int ks = 0; ks < 4; ++ks) {
        const int k0 = ks * 16;
        uint32_t ah[4];
        ah[0] = h2u(__floats2half2_rn(pv[0][4 * ks + 0], pv[0][4 * ks + 1]));
        ah[1] = h2u(__floats2half2_rn(pv[1][4 * ks + 0], pv[1][4 * ks + 1]));
        ah[2] = h2u(__floats2half2_rn(pv[0][4 * ks + 2], pv[0][4 * ks + 3]));
        ah[3] = h2u(__floats2half2_rn(pv[1][4 * ks + 2], pv[1][4 * ks + 3]));
#pragma unroll
        for (int nf = 0; nf < 4; ++nf) {
            const int vo = (nf * 8 + ra) * SVP + k0 + ca2;
            const uint32_t bh0 = *(const uint32_t*)&Vth[vo];
            const uint32_t bh1 = *(const uint32_t*)&Vth[vo + 8];
            mma_f16(oacc[nf], ah, bh0, bh1);
        }
    }

    // ---- write output in (n,H,W,c) layout ----
#pragma unroll
    for (int nf = 0; nf < 4; ++nf)
#pragma unroll
        for (int h = 0; h < 2; ++h) {
            const int i   = m0 + ra + 8 * h;
            const int tok = ((n * 64 + wh * 8 + (i >> 3)) * 64 + ww * 8 + (i & 7));
            float2* dst = (float2*)(out + (size_t)tok * D_MODEL + head * HEAD_DIM
                                    + nf * 8 + ca2);
            *dst = make_float2(oacc[nf][2 * h], oacc[nf][2 * h + 1]);
        }
}

// ---------------------------------------------------------------------------
extern "C" void kernel_launch(void* const* d_in, const int* in_sizes, int n_in,
                              void* d_out, int out_size) {
    const float* x  = (const float*)d_in[0];   // (8,64,64,512) f32
    const float* w  = (const float*)d_in[1];   // (1536,512)   f32
    const float* b  = (const float*)d_in[2];   // (1536,)      f32
    const float* bt = (const float*)d_in[3];   // (225,16)     f32
    float* out = (float*)d_out;                // (8,64,64,512) f32

    __half *xh, *wh, *qh, *ql, *kh, *kl, *vh;
    cudaGetSymbolAddress((void**)&xh, g_xh);
    cudaGetSymbolAddress((void**)&wh, g_wh);
    cudaGetSymbolAddress((void**)&qh, g_qh);
    cudaGetSymbolAddress((void**)&ql, g_ql);
    cudaGetSymbolAddress((void**)&kh, g_kh);
    cudaGetSymbolAddress((void**)&kl, g_kl);
    cudaGetSymbolAddress((void**)&vh, g_vh);

    const int n8x = M_TOK * D_MODEL / 8;       // 2097152
    const int n8w = THREE_D * D_MODEL / 8;     // 98304
    to_half<<<(n8x + 255) / 256, 256>>>(x, xh, n8x);
    to_half<<<(n8w + 255) / 256, 256>>>(w, wh, n8w);

    cudaFuncSetAttribute(qkv_gemm_f16, cudaFuncAttributeMaxDynamicSharedMemorySize,
                         STAGES * STAGEB);
    dim3 g1(THREE_D / 128, M_TOK / 128);       // (12, 256)
    qkv_gemm_f16<<<g1, 256, STAGES * STAGEB>>>(xh, wh, b, qh, ql, kh, kl, vh);

    dim3 g2(N_HEAD, 512);                      // head, window
    win_attn_f16<<<g2, 128>>>(qh, ql, kh, kl, vh, bt, out);
}

// round 17
// speedup vs baseline: 1.0349x; 1.0349x over previous
#include <cuda_runtime.h>
#include <cuda_fp16.h>
#include <cstdint>

#define D_MODEL   512
#define THREE_D   1536
#define M_TOK     32768      // 8 * 64 * 64 tokens
#define N_HEAD    16
#define HEAD_DIM  32
#define SCALE_Q   0.17677669529663689f   // 1/sqrt(32)
#define STAGES    3
#define BK        64         // halves per k-tile
#define NKT       (D_MODEL / BK)        // 8
#define ROWB      144        // smem row stride bytes (64 halves + 16B pad)
#define TILEB     (128 * ROWB)          // 18432 per operand tile
#define STAGEB    (2 * TILEB)           // 36864 per stage

// Device-global scratch (allocation-guard-safe)
__device__ __half g_xh[(size_t)M_TOK * D_MODEL];         // 32 MB  fp16 x
__device__ __half g_wh[(size_t)THREE_D * D_MODEL];       // 1.5 MB fp16 w
// qkv outputs, pre-split fp16 (hi + residual-lo for q,k; hi only for v)
__device__ __half g_qh[(size_t)M_TOK * D_MODEL];
__device__ __half g_ql[(size_t)M_TOK * D_MODEL];
__device__ __half g_kh[(size_t)M_TOK * D_MODEL];
__device__ __half g_kl[(size_t)M_TOK * D_MODEL];
__device__ __half g_vh[(size_t)M_TOK * D_MODEL];

__device__ __forceinline__ void mma_f16(float* c, const uint32_t* a,
                                        uint32_t b0, uint32_t b1) {
    asm volatile(
        "mma.sync.aligned.m16n8k16.row.col.f32.f16.f16.f32 "
        "{%0,%1,%2,%3}, {%4,%5,%6,%7}, {%8,%9}, {%0,%1,%2,%3};\n"
        : "+f"(c[0]), "+f"(c[1]), "+f"(c[2]), "+f"(c[3])
        : "r"(a[0]), "r"(a[1]), "r"(a[2]), "r"(a[3]), "r"(b0), "r"(b1));
}

__device__ __forceinline__ void ldsm4(uint32_t& r0, uint32_t& r1, uint32_t& r2,
                                      uint32_t& r3, uint32_t addr) {
    asm volatile("ldmatrix.sync.aligned.m8n8.x4.shared.b16 {%0,%1,%2,%3}, [%4];"
                 : "=r"(r0), "=r"(r1), "=r"(r2), "=r"(r3) : "r"(addr));
}

__device__ __forceinline__ void ldsm2(uint32_t& r0, uint32_t& r1, uint32_t addr) {
    asm volatile("ldmatrix.sync.aligned.m8n8.x2.shared.b16 {%0,%1}, [%2];"
                 : "=r"(r0), "=r"(r1) : "r"(addr));
}

__device__ __forceinline__ void split_h2(float x, float y, __half2& hi, __half2& lo) {
    hi = __floats2half2_rn(x, y);
    lo = __floats2half2_rn(x - __low2float(hi), y - __high2float(hi));
}

__device__ __forceinline__ uint32_t h2u(__half2 h) {
    return *reinterpret_cast<uint32_t*>(&h);
}

__device__ __forceinline__ void cp16(uint32_t saddr, const void* g) {
    asm volatile("cp.async.cg.shared.global [%0], [%1], 16;"
                 :: "r"(saddr), "l"(g));
}

// ---------------------------------------------------------------------------
// Pre-pass: f32 -> f16 (RN). Each thread converts 8 values (16B store).
// ---------------------------------------------------------------------------
__global__ void to_half(const float* __restrict__ in, __half* __restrict__ out, int n8) {
    int i = blockIdx.x * 256 + threadIdx.x;
    if (i >= n8) return;
    float4 v0 = ((const float4*)in)[2 * i];
    float4 v1 = ((const float4*)in)[2 * i + 1];
    __half2 h[4];
    h[0] = __floats2half2_rn(v0.x, v0.y);
    h[1] = __floats2half2_rn(v0.z, v0.w);
    h[2] = __floats2half2_rn(v1.x, v1.y);
    h[3] = __floats2half2_rn(v1.z, v1.w);
    ((uint4*)out)[i] = *(uint4*)h;
}

// ---------------------------------------------------------------------------
// Kernel 1: qkv = xh @ wh^T + b  (fp16 mma m16n8k16, cp.async 3-stage).
// BK=64: 8 pipeline iterations (half the barriers of BK=32).
// Staged SMEM epilogue -> coalesced 16B fp16 stores.
// ---------------------------------------------------------------------------
#define SROW 132   // f32 stage row stride (128 + 4)

__global__ __launch_bounds__(256, 2)
void qkv_gemm_f16(const __half* __restrict__ xh,
                  const __half* __restrict__ wh,
                  const float* __restrict__ bias_vec,
                  __half* __restrict__ qh, __half* __restrict__ ql,
                  __half* __restrict__ kh, __half* __restrict__ kl,
                  __half* __restrict__ vh) {
    extern __shared__ char smem[];   // STAGES*36864 pipeline, reused as stage
    __shared__ float biasS[128];
    const uint32_t smem_base = (uint32_t)__cvta_generic_to_shared(smem);

    const int tid  = threadIdx.x;
    const int lane = tid & 31, warp = tid >> 5;
    const int wm = warp >> 2, wn = warp & 3;        // 2 x 4 warp grid
    const int bm = blockIdx.y * 128, bn = blockIdx.x * 128;

    if (tid < 128) biasS[tid] = bias_vec[bn + tid];

    // loader: per stage, A 1024 chunks + B 1024 chunks of 16B; 4+4 per thread
    const __half* aptr[4];
    const __half* bptr[4];
    uint32_t soff[4];
#pragma unroll
    for (int i = 0; i < 4; ++i) {
        const int id  = i * 256 + tid;              // 0..1023
        const int row = id >> 3, c = id & 7;
        soff[i] = (uint32_t)(row * ROWB + c * 16);
        aptr[i] = xh + (size_t)(bm + row) * D_MODEL + c * 8;
        bptr[i] = wh + (size_t)(bn + row) * D_MODEL + c * 8;
    }

    auto issue = [&](int kt, int s) {
        const uint32_t ab = smem_base + s * STAGEB;
        const uint32_t bb = ab + TILEB;
#pragma unroll
        for (int i = 0; i < 4; ++i) {
            cp16(ab + soff[i], aptr[i] + kt * BK);
            cp16(bb + soff[i], bptr[i] + kt * BK);
        }
        asm volatile("cp.async.commit_group;");
    };

    float acc[4][4][4];
#pragma unroll
    for (int m = 0; m < 4; ++m)
#pragma unroll
        for (int n = 0; n < 4; ++n)
#pragma unroll
            for (int q = 0; q < 4; ++q) acc[m][n][q] = 0.f;

    const int laneR8 = lane & 7;
    const int aRow   = laneR8 + ((lane >> 3) & 1) * 8;
    const int aChunk = lane >> 4;
    const int bRow   = laneR8;
    const int bChunk = (lane >> 3) & 1;

    issue(0, 0);
    issue(1, 1);

    for (int kt = 0; kt < NKT; ++kt) {
        if (kt == NKT - 1) asm volatile("cp.async.wait_group 0;");
        else               asm volatile("cp.async.wait_group 1;");
        __syncthreads();

        const int s = kt % STAGES;
        const uint32_t abase = smem_base + s * STAGEB;
        const uint32_t bbase = abase + TILEB;

#pragma unroll
        for (int ks = 0; ks < 4; ++ks) {            // four k16 steps per BK=64
            uint32_t af[4][4];
#pragma unroll
            for (int mf = 0; mf < 4; ++mf) {
                const int row = wm * 64 + mf * 16 + aRow;
                ldsm4(af[mf][0], af[mf][1], af[mf][2], af[mf][3],
                      abase + (uint32_t)(row * ROWB + (ks * 2 + aChunk) * 16));
            }
            uint32_t bf[4][2];
#pragma unroll
            for (int nf = 0; nf < 4; ++nf) {
                const int row = wn * 32 + nf * 8 + bRow;
                ldsm2(bf[nf][0], bf[nf][1],
                      bbase + (uint32_t)(row * ROWB + (ks * 2 + bChunk) * 16));
            }
#pragma unroll
            for (int mf = 0; mf < 4; ++mf)
#pragma unroll
                for (int nf = 0; nf < 4; ++nf)
                    mma_f16(acc[mf][nf], af[mf], bf[nf][0], bf[nf][1]);
        }

        if (kt + 2 < NKT) issue(kt + 2, (kt + 2) % STAGES);
    }

    // ---- staged epilogue: 2 passes of 64 rows ----
    const int grp = blockIdx.x >> 2;           // 0=q, 1=k, 2=v
    const int cb  = bn - grp * 512;            // col base within 512-wide array
    const int gq = lane >> 2, tq = lane & 3;
    float* stage = (float*)smem;               // 64 x SROW f32

#pragma unroll
    for (int h = 0; h < 2; ++h) {
        __syncthreads();
        if (wm == h) {
#pragma unroll
            for (int m = 0; m < 4; ++m) {
                const int r0 = m * 16 + gq;
#pragma unroll
                for (int n = 0; n < 4; ++n) {
                    const int c = wn * 32 + n * 8 + tq * 2;
                    *(float2*)&stage[r0 * SROW + c] =
                        make_float2(acc[m][n][0], acc[m][n][1]);
                    *(float2*)&stage[(r0 + 8) * SROW + c] =
                        make_float2(acc[m][n][2], acc[m][n][3]);
                }
            }
        }
        __syncthreads();

#pragma unroll
        for (int u4 = 0; u4 < 4; ++u4) {
            const int u   = u4 * 256 + tid;    // 0..1023
            const int row = u >> 4, ch = u & 15;
            float4 v0 = *(const float4*)&stage[row * SROW + ch * 8];
            float4 v1 = *(const float4*)&stage[row * SROW + ch * 8 + 4];
            float f[8] = {v0.x, v0.y, v0.z, v0.w, v1.x, v1.y, v1.z, v1.w};
#pragma unroll
            for (int i = 0; i < 8; ++i) f[i] += biasS[ch * 8 + i];
            const size_t ga = (size_t)(bm + h * 64 + row) * D_MODEL + cb + ch * 8;
            if (grp == 0) {
#pragma unroll
                for (int i = 0; i < 8; ++i) f[i] *= SCALE_Q;
                __half2 hi[4], lo[4];
#pragma unroll
                for (int i = 0; i < 4; ++i)
                    split_h2(f[2 * i], f[2 * i + 1], hi[i], lo[i]);
                *(uint4*)(qh + ga) = *(uint4*)hi;
                *(uint4*)(ql + ga) = *(uint4*)lo;
            } else if (grp == 1) {
                __half2 hi[4], lo[4];
#pragma unroll
                for (int i = 0; i < 4; ++i)
                    split_h2(f[2 * i], f[2 * i + 1], hi[i], lo[i]);
                *(uint4*)(kh + ga) = *(uint4*)hi;
                *(uint4*)(kl + ga) = *(uint4*)lo;
            } else {
                __half2 hi[4];
#pragma unroll
                for (int i = 0; i < 4; ++i)
                    hi[i] = __floats2half2_rn(f[2 * i], f[2 * i + 1]);
                *(uint4*)(vh + ga) = *(uint4*)hi;
            }
        }
    }
}

// ---------------------------------------------------------------------------
// Kernel 2: per (window, head) attention via fp16 mma.  (R13 config, verbatim)
// ---------------------------------------------------------------------------
__device__ __forceinline__ int region_id(int g) {
    return g < 56 ? 0 : (g < 60 ? 1 : 2);
}

#define SQK 40
#define SVP 72
#define QROWB 80   // attention smem row stride bytes (32 halves + 16B pad)

__global__ __launch_bounds__(128, 7)
void win_attn_f16(const __half* __restrict__ qh, const __half* __restrict__ ql,
                  const __half* __restrict__ kh, const __half* __restrict__ kl,
                  const __half* __restrict__ vh,
                  const float* __restrict__ bias_table, float* __restrict__ out) {
    const int head = blockIdx.x;
    const int wdx  = blockIdx.y;
    const int n  = wdx >> 6;
    const int rr = wdx & 63;
    const int wh = rr >> 3;
    const int ww = rr & 7;

    __shared__ __half Qh[64 * SQK], Ql[64 * SQK];
    __shared__ __half Kh[64 * SQK], Kl[64 * SQK];
    __shared__ __half Vth[32 * SVP];                  // transposed hi: [d][j]
    __shared__ float bias_s[228];

    const int tid  = threadIdx.x;
    const int lane = tid & 31, warp = tid >> 5;
    const int ra  = lane >> 2;
    const int ca2 = (lane & 3) * 2;

    const uint32_t sQh = (uint32_t)__cvta_generic_to_shared(Qh);
    const uint32_t sQl = (uint32_t)__cvta_generic_to_shared(Ql);
    const uint32_t sKh = (uint32_t)__cvta_generic_to_shared(Kh);
    const uint32_t sKl = (uint32_t)__cvta_generic_to_shared(Kl);

    // ---- Q/K hi/lo: direct cp.async copies ----
#pragma unroll
    for (int p = 0; p < 2; ++p) {
        const int u   = p * 128 + tid;              // 0..255
        const int row = u >> 2, c = u & 3;          // row 0..63, 16B chunk 0..3
        const int tok = ((n * 64 + wh * 8 + (row >> 3)) * 64 + ww * 8 + (row & 7));
        const size_t gb = (size_t)tok * D_MODEL + head * HEAD_DIM + c * 8;
        const uint32_t so = (uint32_t)(row * QROWB + c * 16);
        cp16(sQh + so, qh + gb);
        cp16(sQl + so, ql + gb);
        cp16(sKh + so, kh + gb);
        cp16(sKl + so, kl + gb);
    }
    asm volatile("cp.async.commit_group;");

    for (int i = tid; i < 225; i += 128)
        bias_s[i] = bias_table[i * N_HEAD + head];

    // ---- V transposed (hi): PRMT interleave of row pairs ----
#pragma unroll
    for (int pass = 0; pass < 2; ++pass) {
        const int idx = pass * 128 + tid;           // 0..255
        const int jp  = idx & 31;
        const int d4  = (idx >> 5) * 4;
        const int j0  = 2 * jp, j1 = 2 * jp + 1;
        const int t0 = ((n * 64 + wh * 8 + (j0 >> 3)) * 64 + ww * 8 + (j0 & 7));
        const int t1 = ((n * 64 + wh * 8 + (j1 >> 3)) * 64 + ww * 8 + (j1 & 7));
        uint2 a = *(const uint2*)(vh + (size_t)t0 * D_MODEL + head * HEAD_DIM + d4);
        uint2 b = *(const uint2*)(vh + (size_t)t1 * D_MODEL + head * HEAD_DIM + d4);
        *(uint32_t*)&Vth[(d4 + 0) * SVP + j0] = __byte_perm(a.x, b.x, 0x5410);
        *(uint32_t*)&Vth[(d4 + 1) * SVP + j0] = __byte_perm(a.x, b.x, 0x7632);
        *(uint32_t*)&Vth[(d4 + 2) * SVP + j0] = __byte_perm(a.y, b.y, 0x5410);
        *(uint32_t*)&Vth[(d4 + 3) * SVP + j0] = __byte_perm(a.y, b.y, 0x7632);
    }
    asm volatile("cp.async.wait_group 0;");
    __syncthreads();

    const int m0 = warp * 16;

    // ---- phase 1: S = Q K^T (split-fp16, 3 mma per step) ----
    float acc[8][4];
#pragma unroll
    for (int nf = 0; nf < 8; ++nf)
#pragma unroll
        for (int q = 0; q < 4; ++q) acc[nf][q] = 0.f;

#pragma unroll
    for (int ks = 0; ks < 2; ++ks) {
        const int k0 = ks * 16;
        const int ro = (m0 + ra) * SQK + k0 + ca2;
        uint32_t ah[4], al[4];
        ah[0] = *(const uint32_t*)&Qh[ro];
        ah[1] = *(const uint32_t*)&Qh[ro + 8 * SQK];
        ah[2] = *(const uint32_t*)&Qh[ro + 8];
        ah[3] = *(const uint32_t*)&Qh[ro + 8 * SQK + 8];
        al[0] = *(const uint32_t*)&Ql[ro];
        al[1] = *(const uint32_t*)&Ql[ro + 8 * SQK];
        al[2] = *(const uint32_t*)&Ql[ro + 8];
        al[3] = *(const uint32_t*)&Ql[ro + 8 * SQK + 8];
#pragma unroll
        for (int nf = 0; nf < 8; ++nf) {
            const int ko = (nf * 8 + ra) * SQK + k0 + ca2;
            const uint32_t bh0 = *(const uint32_t*)&Kh[ko];
            const uint32_t bh1 = *(const uint32_t*)&Kh[ko + 8];
            const uint32_t bl0 = *(const uint32_t*)&Kl[ko];
            const uint32_t bl1 = *(const uint32_t*)&Kl[ko + 8];
            mma_f16(acc[nf], ah, bh0, bh1);
            mma_f16(acc[nf], ah, bl0, bl1);
            mma_f16(acc[nf], al, bh0, bh1);
        }
    }

    // ---- phase 2: bias + mask + softmax; keep P in registers ----
    float pv[2][16];
#pragma unroll
    for (int h = 0; h < 2; ++h) {
        const int i  = m0 + ra + 8 * h;
        const int ih = i >> 3, iw = i & 7;
        const int mi = region_id(wh * 8 + ih) * 3 + region_id(ww * 8 + iw);

#pragma unroll
        for (int nf = 0; nf < 8; ++nf) {
            const int d0row = (ih - nf + 7) * 15;
            const int regh3 = region_id(wh * 8 + nf) * 3;
#pragma unroll
            for (int e = 0; e < 2; ++e) {
                const int j = ca2 + e;
                float v = acc[nf][2 * h + e] + bias_s[d0row + (iw - j + 7)];
                if (mi != regh3 + region_id(ww * 8 + j)) v -= 100.f;
                pv[h][nf * 2 + e] = v;
            }
        }
        float mx = pv[h][0];
#pragma unroll
        for (int q = 1; q < 16; ++q) mx = fmaxf(mx, pv[h][q]);
        mx = fmaxf(mx, __shfl_xor_sync(0xffffffffu, mx, 1));
        mx = fmaxf(mx, __shfl_xor_sync(0xffffffffu, mx, 2));
        float sum = 0.f;
#pragma unroll
        for (int q = 0; q < 16; ++q) { pv[h][q] = __expf(pv[h][q] - mx); sum += pv[h][q]; }
        sum += __shfl_xor_sync(0xffffffffu, sum, 1);
        sum += __shfl_xor_sync(0xffffffffu, sum, 2);
        const float inv = 1.0f / sum;
#pragma unroll
        for (int q = 0; q < 16; ++q) pv[h][q] *= inv;
    }

    // ---- phase 3: O = P V  (hi-fp16) ----
    float oacc[4][4];
#pragma unroll
    for (int nf = 0; nf < 4; ++nf)
#pragma unroll
        for (int q = 0; q < 4; ++q) oacc[nf][q] = 0.f;

#pragma unroll
    for (int ks = 0; ks < 4; ++ks) {
        const int k0 = ks * 16;
        uint32_t ah[4];
        ah[0] = h2u(__floats2half2_rn(pv[0][4 * ks + 0], pv[0][4 * ks + 1]));
        ah[1] = h2u(__floats2half2_rn(pv[1][4 * ks + 0], pv[1][4 * ks + 1]));
        ah[2] = h2u(__floats2half2_rn(pv[0][4 * ks + 2], pv[0][4 * ks + 3]));
        ah[3] = h2u(__floats2half2_rn(pv[1][4 * ks + 2], pv[1][4 * ks + 3]));
#pragma unroll
        for (int nf = 0; nf < 4; ++nf) {
            const int vo = (nf * 8 + ra) * SVP + k0 + ca2;
            const uint32_t bh0 = *(const uint32_t*)&Vth[vo];
            const uint32_t bh1 = *(const uint32_t*)&Vth[vo + 8];
            mma_f16(oacc[nf], ah, bh0, bh1);
        }
    }

    // ---- write output in (n,H,W,c) layout ----
#pragma unroll
    for (int nf = 0; nf < 4; ++nf)
#pragma unroll
        for (int h = 0; h < 2; ++h) {
            const int i   = m0 + ra + 8 * h;
            const int tok = ((n * 64 + wh * 8 + (i >> 3)) * 64 + ww * 8 + (i & 7));
            float2* dst = (float2*)(out + (size_t)tok * D_MODEL + head * HEAD_DIM
                                    + nf * 8 + ca2);
            *dst = make_float2(oacc[nf][2 * h], oacc[nf][2 * h + 1]);
        }
}

// ---------------------------------------------------------------------------
extern "C" void kernel_launch(void* const* d_in, const int* in_sizes, int n_in,
                              void* d_out, int out_size) {
    const float* x  = (const float*)d_in[0];   // (8,64,64,512) f32
    const float* w  = (const float*)d_in[1];   // (1536,512)   f32
    const float* b  = (const float*)d_in[2];   // (1536,)      f32
    const float* bt = (const float*)d_in[3];   // (225,16)     f32
    float* out = (float*)d_out;                // (8,64,64,512) f32

    __half *xh, *wh, *qh, *ql, *kh, *kl, *vh;
    cudaGetSymbolAddress((void**)&xh, g_xh);
    cudaGetSymbolAddress((void**)&wh, g_wh);
    cudaGetSymbolAddress((void**)&qh, g_qh);
    cudaGetSymbolAddress((void**)&ql, g_ql);
    cudaGetSymbolAddress((void**)&kh, g_kh);
    cudaGetSymbolAddress((void**)&kl, g_kl);
    cudaGetSymbolAddress((void**)&vh, g_vh);

    const int n8x = M_TOK * D_MODEL / 8;       // 2097152
    const int n8w = THREE_D * D_MODEL / 8;     // 98304
    to_half<<<(n8x + 255) / 256, 256>>>(x, xh, n8x);
    to_half<<<(n8w + 255) / 256, 256>>>(w, wh, n8w);

    cudaFuncSetAttribute(qkv_gemm_f16, cudaFuncAttributeMaxDynamicSharedMemorySize,
                         STAGES * STAGEB);
    dim3 g1(THREE_D / 128, M_TOK / 128);       // (12, 256)
    qkv_gemm_f16<<<g1, 256, STAGES * STAGEB>>>(xh, wh, b, qh, ql, kh, kl, vh);

    dim3 g2(N_HEAD, 512);                      // head, window
    win_attn_f16<<<g2, 128>>>(qh, ql, kh, kl, vh, bt, out);
}